// round 5
// baseline (speedup 1.0000x reference)
#include <cuda_runtime.h>
#include <math.h>
#include <stdint.h>

#define TB 8
#define TS 4096
#define TD 512
#define TH 2048
#define TE 8
#define TP 16
#define NTOK (TB*TS)          /* 32768 tokens */

/* ---------------- device state ---------------- */
__device__ int    g_counts[TE];
__device__ int    g_base[TE];
__device__ int    g_tok[TE * NTOK];
__device__ float  g_gate[TE * NTOK];
__device__ double g_zsum;
__device__ double g_psum[TE];
__device__ float  g_H[(size_t)2 * NTOK * TH];     /* tf32-rounded H */
__device__ float  g_xt[(size_t)NTOK * TD];        /* tf32-rounded x */
__device__ float  g_w1t[(size_t)TE * TH * TD];    /* W1^T: [e][h][d] (K-major) */
__device__ float  g_w3t[(size_t)TE * TH * TD];    /* W3^T: [e][h][d] */
__device__ float  g_w2t[(size_t)TE * TD * TH];    /* W2^T: [e][d][h] */

/* ---------------- helpers ---------------- */
__device__ __forceinline__ unsigned tf32_of(float f) {
    unsigned u; asm("cvt.rna.tf32.f32 %0, %1;" : "=r"(u) : "f"(f)); return u;
}
__device__ __forceinline__ float tf32f(float f) { return __uint_as_float(tf32_of(f)); }

__device__ __forceinline__ void mma_tf32(
    float& c0, float& c1, float& c2, float& c3,
    unsigned a0, unsigned a1, unsigned a2, unsigned a3,
    unsigned b0, unsigned b1)
{
    asm volatile(
        "mma.sync.aligned.m16n8k8.row.col.f32.tf32.tf32.f32 "
        "{%0,%1,%2,%3}, {%4,%5,%6,%7}, {%8,%9}, {%0,%1,%2,%3};"
        : "+f"(c0), "+f"(c1), "+f"(c2), "+f"(c3)
        : "r"(a0), "r"(a1), "r"(a2), "r"(a3), "r"(b0), "r"(b1));
}

#define CP16(dst, src) \
    asm volatile("cp.async.cg.shared.global [%0], [%1], 16;" :: "r"(dst), "l"(src))
#define CP_COMMIT() asm volatile("cp.async.commit_group;")
#define CP_WAIT1()  asm volatile("cp.async.wait_group 1;")
#define CP_WAIT0()  asm volatile("cp.async.wait_group 0;")

__device__ __forceinline__ unsigned sptr(const void* p) {
    return (unsigned)__cvta_generic_to_shared(p);
}
__device__ __forceinline__ uint32_t swz128(uint32_t byte_off) {
    return byte_off ^ ((byte_off >> 3) & 0x70);
}

#define HDR 2048
#define F_STG 49152
#define FFN_SMEM (HDR + 3 * F_STG)   /* 149504 B */

/* ---------------- prep: transpose+round weights, round x, zero state ---------------- */
__global__ __launch_bounds__(256) void prep_kernel(
    const float* __restrict__ x, const float* __restrict__ W1,
    const float* __restrict__ W2, const float* __restrict__ W3)
{
    const int m = blockIdx.z;
    const int tx = threadIdx.x, ty = threadIdx.y;
    if (m < 24) {
        const float* src; float* dst; int R, C;
        if (m < 8)       { src = W1 + (size_t)m * TD * TH;        dst = g_w1t + (size_t)m * TH * TD;        R = TD; C = TH; }
        else if (m < 16) { src = W3 + (size_t)(m - 8) * TD * TH;  dst = g_w3t + (size_t)(m - 8) * TH * TD;  R = TD; C = TH; }
        else             { src = W2 + (size_t)(m - 16) * TH * TD; dst = g_w2t + (size_t)(m - 16) * TD * TH; R = TH; C = TD; }
        const int bx = blockIdx.x, by = blockIdx.y;
        if (bx * 32 >= C || by * 32 >= R) return;
        __shared__ float t[32][33];
        #pragma unroll
        for (int i = 0; i < 4; ++i)
            t[ty + 8 * i][tx] = src[(size_t)(by * 32 + ty + 8 * i) * C + bx * 32 + tx];
        __syncthreads();
        #pragma unroll
        for (int i = 0; i < 4; ++i)
            dst[(size_t)(bx * 32 + ty + 8 * i) * R + by * 32 + tx] = tf32f(t[tx][ty + 8 * i]);
    } else {
        const int tid = ty * 32 + tx;
        const size_t nb = (size_t)blockIdx.y * 64 + blockIdx.x;   /* 0..4095 */
        if (nb == 0 && tid < TE) { g_counts[tid] = 0; g_psum[tid] = 0.0; if (tid == 0) g_zsum = 0.0; }
        const size_t NX = (size_t)NTOK * TD / 4;
        const size_t stride = (size_t)4096 * 256;
        for (size_t i = nb * 256 + tid; i < NX; i += stride) {
            float4 v = ((const float4*)x)[i];
            v.x = tf32f(v.x); v.y = tf32f(v.y); v.z = tf32f(v.z); v.w = tf32f(v.w);
            ((float4*)g_xt)[i] = v;
        }
    }
}

/* ---------------- router (unchanged, passing) ---------------- */
__global__ __launch_bounds__(256) void router_kernel(
    const float* __restrict__ x, const int* __restrict__ pid,
    const float* __restrict__ Wr, const float* __restrict__ Wp)
{
    __shared__ float sWrT[TE * TD];
    __shared__ float sPsum[TE];
    __shared__ float sZsum;
    __shared__ int   sCnt[TE];
    __shared__ int   sGbase[TE];
    __shared__ unsigned char sE[256];
    __shared__ short sSlot[256];
    __shared__ float sG[256];

    const int tid = threadIdx.x;
    for (int idx = tid; idx < TD * TE; idx += 256) {
        int d = idx >> 3, e = idx & 7;
        sWrT[e * TD + d] = Wr[idx];
    }
    if (tid < TE) { sPsum[tid] = 0.f; sCnt[tid] = 0; }
    if (tid == 0) sZsum = 0.f;
    __syncthreads();

    const int warp = tid >> 5, lane = tid & 31;
    const int tok0 = blockIdx.x * 128 + warp * 16;

    for (int tt = 0; tt < 16; ++tt) {
        const int t = tok0 + tt;
        float acc[TE];
        #pragma unroll
        for (int e = 0; e < TE; ++e) acc[e] = 0.f;
        const float* xr = x + (size_t)t * TD;
        for (int i = lane; i < TD; i += 32) {
            float xv = xr[i];
            #pragma unroll
            for (int e = 0; e < TE; ++e)
                acc[e] = fmaf(xv, sWrT[e * TD + i], acc[e]);
        }
        #pragma unroll
        for (int off = 16; off >= 1; off >>= 1) {
            #pragma unroll
            for (int e = 0; e < TE; ++e)
                acc[e] += __shfl_down_sync(0xffffffffu, acc[e], off);
        }
        if (lane == 0) {
            const int b = t / TS;
            const int p = pid[b];
            float l[TE];
            float zs = 0.f, mx = -1e30f;
            #pragma unroll
            for (int e = 0; e < TE; ++e) {
                l[e] = acc[e] + Wp[p * TE + e];
                zs += l[e] * l[e];
                mx = fmaxf(mx, l[e]);
            }
            atomicAdd(&sZsum, zs);
            float s = 0.f, pr[TE];
            #pragma unroll
            for (int e = 0; e < TE; ++e) { pr[e] = expf(l[e] - mx); s += pr[e]; }
            const float inv = 1.f / s;
            #pragma unroll
            for (int e = 0; e < TE; ++e) atomicAdd(&sPsum[e], pr[e] * inv);
            int i0 = 0;
            #pragma unroll
            for (int e = 1; e < TE; ++e) if (l[e] > l[i0]) i0 = e;
            int i1 = (i0 == 0) ? 1 : 0;
            #pragma unroll
            for (int e = 0; e < TE; ++e) if (e != i0 && l[e] > l[i1]) i1 = e;
            const float e1 = expf(l[i1] - l[i0]);
            const float g0 = 1.f / (1.f + e1);
            const float g1 = e1 * g0;
            const int s0 = atomicAdd(&sCnt[i0], 1);
            const int s1 = atomicAdd(&sCnt[i1], 1);
            const int loc = (warp * 16 + tt) * 2;
            sE[loc]     = (unsigned char)i0; sSlot[loc]     = (short)s0; sG[loc]     = g0;
            sE[loc + 1] = (unsigned char)i1; sSlot[loc + 1] = (short)s1; sG[loc + 1] = g1;
        }
    }
    __syncthreads();
    if (tid < TE) {
        sGbase[tid] = atomicAdd(&g_counts[tid], sCnt[tid]);
        atomicAdd(&g_psum[tid], (double)sPsum[tid]);
    }
    if (tid == 0) atomicAdd(&g_zsum, (double)sZsum);
    __syncthreads();
    {
        const int e = sE[tid];
        const int pos = sGbase[e] + sSlot[tid];
        const int t = blockIdx.x * 128 + (tid >> 1);
        g_tok[e * NTOK + pos]  = t;
        g_gate[e * NTOK + pos] = sG[tid];
    }
}

__global__ void prefix_kernel() {
    if (threadIdx.x == 0) {
        int s = 0;
        for (int e = 0; e < TE; ++e) { g_base[e] = s; s += g_counts[e]; }
    }
}

/* ================= FFN stage 1: H = (X@W1) * silu(X@W3) =================
   CTA tile 128(M) x 128(N), both gemms. BK=32, 16 iters, 3-stage cp.async.
   8 warps = 2m x 4n; warp tile 64x32 per gemm -> m_frags=4, n_frags=4.
   Stage smem 48KB: A[128][32] @0, B1[128n][32k] @16K, B3 @32K; all SW128 swizzled. */
__global__ __launch_bounds__(256, 1) void ffn1_kernel()
{
    const int e   = blockIdx.z;
    const int cnt = g_counts[e];
    const int m0  = blockIdx.x * 128;
    if (m0 >= cnt) return;
    const int n0   = blockIdx.y * 128;
    const int base = g_base[e];

    extern __shared__ char smc[];
    int* stok = (int*)smc;

    const int tid = threadIdx.x;
    if (tid < 128) {
        const int r = m0 + tid;
        stok[tid] = (r < cnt) ? g_tok[e * NTOK + r] : g_tok[e * NTOK];
    }
    __syncthreads();

    const float* W1e = g_w1t + (size_t)e * TH * TD;
    const float* W3e = g_w3t + (size_t)e * TH * TD;

    const int warp = tid >> 5, lane = tid & 31;
    const int warp_m = warp >> 2;      /* 0..1 -> *64 */
    const int warp_n = warp & 3;       /* 0..3 -> *32 */
    const int lg = lane >> 2, lt = lane & 3;

    auto issue = [&](int it, int stg) {
        const int k0 = it * 32;
        char* S = smc + HDR + stg * F_STG;
        #pragma unroll
        for (int j = 0; j < 4; ++j) {
            const int q = tid + 256 * j;
            const int row = q >> 3, c = q & 7;
            const uint32_t sw = swz128(row * 128 + c * 16);
            CP16(sptr(S + sw),         g_xt + (size_t)stok[row] * TD + k0 + c * 4);
            CP16(sptr(S + 16384 + sw), W1e + (size_t)(n0 + row) * TD + k0 + c * 4);
            CP16(sptr(S + 32768 + sw), W3e + (size_t)(n0 + row) * TD + k0 + c * 4);
        }
        CP_COMMIT();
    };

    float acc1[4][4][4], acc3[4][4][4];
    #pragma unroll
    for (int i = 0; i < 4; ++i)
        #pragma unroll
        for (int j = 0; j < 4; ++j)
            #pragma unroll
            for (int k = 0; k < 4; ++k) { acc1[i][j][k] = 0.f; acc3[i][j][k] = 0.f; }

    issue(0, 0);
    issue(1, 1);
    int sa = 0, sc = 2;
    const int NIT = TD / 32;   /* 16 */

    #pragma unroll 1
    for (int it = 0; it < NIT; ++it) {
        if (it < NIT - 1) { CP_WAIT1(); } else { CP_WAIT0(); }
        __syncthreads();

        const float* A  = (const float*)(smc + HDR + sa * F_STG);
        const float* B1 = A + 4096;
        const float* B3 = A + 8192;

        #pragma unroll
        for (int ks = 0; ks < 4; ++ks) {
            const int c0  = 2 * ks;
            const int xo0 = ((c0 ^ lg) << 2) + lt;
            const int xo1 = (((c0 + 1) ^ lg) << 2) + lt;
            unsigned a[4][4];
            #pragma unroll
            for (int mi = 0; mi < 4; ++mi) {
                const int r0 = (warp_m * 64 + mi * 16 + lg) * 32;
                a[mi][0] = __float_as_uint(A[r0 + xo0]);
                a[mi][1] = __float_as_uint(A[r0 + 256 + xo0]);   /* +8 rows */
                a[mi][2] = __float_as_uint(A[r0 + xo1]);
                a[mi][3] = __float_as_uint(A[r0 + 256 + xo1]);
            }
            unsigned b1f[4][2], b3f[4][2];
            #pragma unroll
            for (int ni = 0; ni < 4; ++ni) {
                const int nr = (warp_n * 32 + ni * 8 + lg) * 32;
                b1f[ni][0] = __float_as_uint(B1[nr + xo0]);
                b1f[ni][1] = __float_as_uint(B1[nr + xo1]);
                b3f[ni][0] = __float_as_uint(B3[nr + xo0]);
                b3f[ni][1] = __float_as_uint(B3[nr + xo1]);
            }
            #pragma unroll
            for (int mi = 0; mi < 4; ++mi)
                #pragma unroll
                for (int ni = 0; ni < 4; ++ni) {
                    mma_tf32(acc1[mi][ni][0], acc1[mi][ni][1], acc1[mi][ni][2], acc1[mi][ni][3],
                             a[mi][0], a[mi][1], a[mi][2], a[mi][3], b1f[ni][0], b1f[ni][1]);
                    mma_tf32(acc3[mi][ni][0], acc3[mi][ni][1], acc3[mi][ni][2], acc3[mi][ni][3],
                             a[mi][0], a[mi][1], a[mi][2], a[mi][3], b3f[ni][0], b3f[ni][1]);
                }
        }

        if (it + 2 < NIT) issue(it + 2, sc);
        if (++sa == 3) sa = 0;
        if (++sc == 3) sc = 0;
    }

    /* epilogue: h = (X@W1) * silu(X@W3), tf32-rounded for ffn2 */
    #pragma unroll
    for (int mi = 0; mi < 4; ++mi) {
        #pragma unroll
        for (int half = 0; half < 2; ++half) {
            const int rl = warp_m * 64 + mi * 16 + half * 8 + lg;
            const int r  = m0 + rl;
            if (r < cnt) {
                float* hrow = g_H + (size_t)(base + r) * TH + n0 + warp_n * 32;
                #pragma unroll
                for (int ni = 0; ni < 4; ++ni) {
                    const float g1v = acc1[mi][ni][half * 2 + 0];
                    const float g1w = acc1[mi][ni][half * 2 + 1];
                    const float g3v = acc3[mi][ni][half * 2 + 0];
                    const float g3w = acc3[mi][ni][half * 2 + 1];
                    float2 h;
                    h.x = tf32f(g1v * (g3v / (1.f + expf(-g3v))));
                    h.y = tf32f(g1w * (g3w / (1.f + expf(-g3w))));
                    *(float2*)(hrow + ni * 8 + 2 * lt) = h;
                }
            }
        }
    }
}

/* ================= FFN stage 2: y += gate * (H @ W2) =================
   CTA tile 128(M) x 256(N). BK=32, 64 iters, 3-stage cp.async.
   8 warps = 2m x 4n; warp tile 64x64 -> m_frags=4, n_frags=8.
   Stage smem 48KB: A(H)[128][32] @0, B(W2)[256n][32k] @16K. */
__global__ __launch_bounds__(256, 1) void ffn2_kernel(float* __restrict__ y)
{
    const int e   = blockIdx.z;
    const int cnt = g_counts[e];
    const int m0  = blockIdx.x * 128;
    if (m0 >= cnt) return;
    const int n0   = blockIdx.y * 256;
    const int base = g_base[e];

    extern __shared__ char smc[];
    int*   sslot = (int*)smc;           /* 128 */
    int*   stokT = (int*)(smc + 512);   /* 128 */
    float* sgate = (float*)(smc + 1024);/* 128 */

    const int tid = threadIdx.x;
    if (tid < 128) {
        const int r = m0 + tid;
        const int rc = (r < cnt) ? r : (cnt - 1);
        sslot[tid] = base + rc;
        stokT[tid] = g_tok[e * NTOK + rc];
        sgate[tid] = (r < cnt) ? g_gate[e * NTOK + r] : 0.f;
    }
    __syncthreads();

    const float* W2e = g_w2t + (size_t)e * TD * TH;

    const int warp = tid >> 5, lane = tid & 31;
    const int warp_m = warp >> 2;      /* 0..1 -> *64 */
    const int warp_n = warp & 3;       /* 0..3 -> *64 */
    const int lg = lane >> 2, lt = lane & 3;

    auto issue = [&](int it, int stg) {
        const int k0 = it * 32;
        char* S = smc + HDR + stg * F_STG;
        #pragma unroll
        for (int j = 0; j < 4; ++j) {      /* H: 1024 chunks */
            const int q = tid + 256 * j;
            const int row = q >> 3, c = q & 7;
            CP16(sptr(S + swz128(row * 128 + c * 16)),
                 g_H + (size_t)sslot[row] * TH + k0 + c * 4);
        }
        #pragma unroll
        for (int j = 0; j < 8; ++j) {      /* W2: 2048 chunks */
            const int q = tid + 256 * j;
            const int row = q >> 3, c = q & 7;
            CP16(sptr(S + 16384 + swz128(row * 128 + c * 16)),
                 W2e + (size_t)(n0 + row) * TH + k0 + c * 4);
        }
        CP_COMMIT();
    };

    float acc[4][8][4];
    #pragma unroll
    for (int i = 0; i < 4; ++i)
        #pragma unroll
        for (int j = 0; j < 8; ++j)
            #pragma unroll
            for (int k = 0; k < 4; ++k) acc[i][j][k] = 0.f;

    issue(0, 0);
    issue(1, 1);
    int sa = 0, sc = 2;
    const int NIT = TH / 32;   /* 64 */

    #pragma unroll 1
    for (int it = 0; it < NIT; ++it) {
        if (it < NIT - 1) { CP_WAIT1(); } else { CP_WAIT0(); }
        __syncthreads();

        const float* A = (const float*)(smc + HDR + sa * F_STG);
        const float* B = A + 4096;

        #pragma unroll
        for (int ks = 0; ks < 4; ++ks) {
            const int c0  = 2 * ks;
            const int xo0 = ((c0 ^ lg) << 2) + lt;
            const int xo1 = (((c0 + 1) ^ lg) << 2) + lt;
            unsigned a[4][4];
            #pragma unroll
            for (int mi = 0; mi < 4; ++mi) {
                const int r0 = (warp_m * 64 + mi * 16 + lg) * 32;
                a[mi][0] = __float_as_uint(A[r0 + xo0]);
                a[mi][1] = __float_as_uint(A[r0 + 256 + xo0]);
                a[mi][2] = __float_as_uint(A[r0 + xo1]);
                a[mi][3] = __float_as_uint(A[r0 + 256 + xo1]);
            }
            unsigned b[8][2];
            #pragma unroll
            for (int ni = 0; ni < 8; ++ni) {
                const int nr = (warp_n * 64 + ni * 8 + lg) * 32;
                b[ni][0] = __float_as_uint(B[nr + xo0]);
                b[ni][1] = __float_as_uint(B[nr + xo1]);
            }
            #pragma unroll
            for (int mi = 0; mi < 4; ++mi)
                #pragma unroll
                for (int ni = 0; ni < 8; ++ni)
                    mma_tf32(acc[mi][ni][0], acc[mi][ni][1], acc[mi][ni][2], acc[mi][ni][3],
                             a[mi][0], a[mi][1], a[mi][2], a[mi][3], b[ni][0], b[ni][1]);
        }

        if (it + 2 < NIT) issue(it + 2, sc);
        if (++sa == 3) sa = 0;
        if (++sc == 3) sc = 0;
    }

    #pragma unroll
    for (int mi = 0; mi < 4; ++mi) {
        #pragma unroll
        for (int half = 0; half < 2; ++half) {
            const int rl = warp_m * 64 + mi * 16 + half * 8 + lg;
            if (m0 + rl < cnt) {
                const int t = stokT[rl];
                const float g = sgate[rl];
                float* yr = y + (size_t)t * TD + n0 + warp_n * 64;
                #pragma unroll
                for (int ni = 0; ni < 8; ++ni) {
                    const int col = ni * 8 + 2 * lt;
                    atomicAdd(&yr[col],     g * acc[mi][ni][half * 2 + 0]);
                    atomicAdd(&yr[col + 1], g * acc[mi][ni][half * 2 + 1]);
                }
            }
        }
    }
}

/* ---------------- losses ---------------- */
__global__ void losses_kernel(const float* __restrict__ Wp, float* __restrict__ out, int sbase)
{
    if (threadIdx.x != 0) return;
    const double z = g_zsum / (double)((size_t)NTOK * TE) * 0.001;
    double sb = 0.0;
    for (int e = 0; e < TE; ++e) {
        const double m = g_psum[e] / (double)NTOK;
        const double d = m - 1.0 / TE;
        sb += d * d;
    }
    sb /= TE;
    float Pn[TP][TE];
    for (int p = 0; p < TP; ++p) {
        float mx = -1e30f;
        for (int e = 0; e < TE; ++e) mx = fmaxf(mx, Wp[p * TE + e]);
        float s = 0.f;
        for (int e = 0; e < TE; ++e) { Pn[p][e] = expf(Wp[p * TE + e] - mx); s += Pn[p][e]; }
        const float inv = 1.f / s;
        for (int e = 0; e < TE; ++e) Pn[p][e] *= inv;
    }
    double acc = 0.0;
    for (int p = 0; p < TP; ++p)
        for (int q = 0; q < TP; ++q)
            if (p != q) {
                float d = 0.f;
                for (int e = 0; e < TE; ++e) d += Pn[p][e] * Pn[q][e];
                acc += (double)d;
            }
    const double spec = acc / (double)(TP * TP) * 0.1;
    out[sbase + 0] = (float)z;
    out[sbase + 1] = (float)sb;
    out[sbase + 2] = (float)spec;
}

/* ---------------- launch ---------------- */
extern "C" void kernel_launch(void* const* d_in, const int* in_sizes, int n_in,
                              void* d_out, int out_size)
{
    const float* x  = (const float*)d_in[0];
    const int*   pid= (const int*)  d_in[1];
    const float* Wr = (const float*)d_in[2];
    const float* Wp = (const float*)d_in[3];
    const float* W1 = (const float*)d_in[4];
    const float* W2 = (const float*)d_in[5];
    const float* W3 = (const float*)d_in[6];
    float* out = (float*)d_out;

    static int attr_done = 0;
    if (!attr_done) {
        cudaFuncSetAttribute(ffn1_kernel, cudaFuncAttributeMaxDynamicSharedMemorySize, FFN_SMEM);
        cudaFuncSetAttribute(ffn2_kernel, cudaFuncAttributeMaxDynamicSharedMemorySize, FFN_SMEM);
        attr_done = 1;
    }

    cudaMemsetAsync(d_out, 0, (size_t)out_size * sizeof(float));
    {
        dim3 gP(64, 64, 25), bP(32, 8);
        prep_kernel<<<gP, bP>>>(x, W1, W2, W3);
    }
    router_kernel<<<NTOK / 128, 256>>>(x, pid, Wr, Wp);
    prefix_kernel<<<1, 1>>>();

    dim3 gA(NTOK / 128, TH / 128, TE);
    ffn1_kernel<<<gA, 256, FFN_SMEM>>>();

    dim3 gB(NTOK / 128, TD / 256, TE);
    ffn2_kernel<<<gB, 256, FFN_SMEM>>>(out);

    losses_kernel<<<1, 1>>>(Wp, out, out_size - 3);
}